// round 5
// baseline (speedup 1.0000x reference)
#include <cuda_runtime.h>
#include <cuda_bf16.h>
#include <cstddef>

// ---------------------------------------------------------------------------
// GCN: 4x GraphConv (agg = adj@h ; h' = act(concat(h,agg)@W + b)) + MLP head.
// fp32 SIMT GEMM: 128x128 block tile, BK=16, 8x8 per thread with split
// fragments (conflict-free LDS.128), register-prefetch double buffering.
// Concat is virtual (two A pointers split at K1). Bias+ReLU/PReLU fused.
// ---------------------------------------------------------------------------

#define BM 128
#define BN 128
#define BK 16

static const int Bb   = 32;
static const int Nn   = 1024;
static const int D0   = 256;
static const int H    = 512;
static const int HH   = 256;

// Scratch (device globals; allocation-free)
__device__ float g_bufA[32u * 1024u * 512u];
__device__ float g_bufB[32u * 1024u * 512u];
__device__ float g_agg [32u * 1024u * 512u];

// C[b] = act( [A1[b] | A2[b]] @ W[b] + bias )
//   A1: [M,K1] row-major, batch stride sA1 (elements)
//   A2: [M,K2] row-major, batch stride sA2 (may be null, K2=0)
//   W : [K1+K2, F] row-major, batch stride sW (0 => shared weights)
//   act: 0=none, 1=relu, 2=prelu(alpha per output channel)
// Requirements: M%128==0, F%128==0, K1%16==0, K2%16==0 (all satisfied here).
__global__ __launch_bounds__(256, 2)
void gemm_cat_kernel(const float* __restrict__ A1, size_t sA1, int K1,
                     const float* __restrict__ A2, size_t sA2, int K2,
                     const float* __restrict__ W,  size_t sW,
                     const float* __restrict__ bias,
                     const float* __restrict__ alpha,
                     float* __restrict__ C, size_t sC,
                     int M, int F, int act)
{
    __shared__ float As[BK][BM];   // A stored transposed: As[k][m]
    __shared__ float Bs[BK][BN];

    const int b  = blockIdx.z;
    const float* A1b = A1 + (size_t)b * sA1;
    const float* A2b = A2 ? (A2 + (size_t)b * sA2) : nullptr;
    const float* Wb  = W  + (size_t)b * sW;
    float*       Cb  = C  + (size_t)b * sC;

    const int m0 = blockIdx.y * BM;
    const int n0 = blockIdx.x * BN;

    const int tid = threadIdx.x;
    const int tx  = tid & 15;      // 0..15  -> column fragment selector
    const int ty  = tid >> 4;      // 0..15  -> row fragment selector
    const int Ktot = K1 + K2;

    // A-load mapping: 128 rows x 16 cols, float4 per thread, 2 rows 64 apart
    const int arow  = tid >> 2;          // 0..63
    const int acol4 = (tid & 3) * 4;     // 0,4,8,12
    // B-load mapping: 16 rows x 128 cols, float4 per thread, 2 rows 8 apart
    const int brow  = tid >> 5;          // 0..7
    const int bcol4 = (tid & 31) * 4;    // 0..124

    float acc[8][8];
    #pragma unroll
    for (int i = 0; i < 8; i++)
        #pragma unroll
        for (int j = 0; j < 8; j++) acc[i][j] = 0.f;

    // ---- global-load helper (prefetch into registers) ----
    float4 vA0, vA1, vB0, vB1;
    auto load_tile = [&](int kt) {
        const float* Asrc; int lda; int kofs;
        if (kt < K1) { Asrc = A1b; lda = K1; kofs = kt; }
        else         { Asrc = A2b; lda = K2; kofs = kt - K1; }
        const float* abase = Asrc + (size_t)m0 * lda + kofs + acol4;
        vA0 = *(const float4*)(abase + (size_t)arow * lda);
        vA1 = *(const float4*)(abase + (size_t)(arow + 64) * lda);
        const float* bbase = Wb + (size_t)kt * F + n0 + bcol4;
        vB0 = *(const float4*)(bbase + (size_t)brow * F);
        vB1 = *(const float4*)(bbase + (size_t)(brow + 8) * F);
    };
    auto store_tile = [&]() {
        As[acol4 + 0][arow] = vA0.x;  As[acol4 + 1][arow] = vA0.y;
        As[acol4 + 2][arow] = vA0.z;  As[acol4 + 3][arow] = vA0.w;
        As[acol4 + 0][arow + 64] = vA1.x;  As[acol4 + 1][arow + 64] = vA1.y;
        As[acol4 + 2][arow + 64] = vA1.z;  As[acol4 + 3][arow + 64] = vA1.w;
        *(float4*)&Bs[brow][bcol4]     = vB0;
        *(float4*)&Bs[brow + 8][bcol4] = vB1;
    };

    load_tile(0);
    for (int kt = 0; kt < Ktot; kt += BK) {
        store_tile();
        __syncthreads();
        if (kt + BK < Ktot) load_tile(kt + BK);

        #pragma unroll
        for (int kk = 0; kk < BK; kk++) {
            // split fragments: rows {ty*4..}, {64+ty*4..}; cols {tx*4..}, {64+tx*4..}
            float4 a0 = *(const float4*)&As[kk][ty * 4];
            float4 a1 = *(const float4*)&As[kk][64 + ty * 4];
            float4 b0 = *(const float4*)&Bs[kk][tx * 4];
            float4 b1 = *(const float4*)&Bs[kk][64 + tx * 4];
            float a[8] = {a0.x, a0.y, a0.z, a0.w, a1.x, a1.y, a1.z, a1.w};
            float bb[8] = {b0.x, b0.y, b0.z, b0.w, b1.x, b1.y, b1.z, b1.w};
            #pragma unroll
            for (int i = 0; i < 8; i++)
                #pragma unroll
                for (int j = 0; j < 8; j++)
                    acc[i][j] = fmaf(a[i], bb[j], acc[i][j]);
        }
        __syncthreads();
    }

    // Epilogue: bias + activation, two float4 stores per row fragment
    #pragma unroll
    for (int i = 0; i < 8; i++) {
        int row = m0 + ((i < 4) ? (ty * 4 + i) : (64 + ty * 4 + (i - 4)));
        #pragma unroll
        for (int half = 0; half < 2; half++) {
            int colbase = n0 + half * 64 + tx * 4;
            float4 v;
            float* vp = &v.x;
            #pragma unroll
            for (int q = 0; q < 4; q++) {
                int j = half * 4 + q;
                float val = acc[i][j];
                int col = colbase + q;
                if (bias)          val += bias[col];
                if (act == 1)      val = val > 0.f ? val : 0.f;
                else if (act == 2) val = val > 0.f ? val : alpha[col] * val;
                vp[q] = val;
            }
            *(float4*)(Cb + (size_t)row * F + colbase) = v;
        }
    }
}

// Final projection: out[m, 0:2] = h[m,:] @ cW2 + cb2   (K=256, F=2)
__global__ __launch_bounds__(256)
void final_proj_kernel(const float* __restrict__ h,
                       const float* __restrict__ cW2,  // [K,2] row-major
                       const float* __restrict__ cb2,
                       float* __restrict__ out, int Mrows, int K)
{
    int m = blockIdx.x * blockDim.x + threadIdx.x;
    if (m >= Mrows) return;
    const float4* hr = (const float4*)(h + (size_t)m * K);
    float s0 = cb2[0], s1 = cb2[1];
    #pragma unroll 4
    for (int k4 = 0; k4 < K / 4; k4++) {
        float4 v = hr[k4];
        const float* w = cW2 + 8 * k4;
        s0 = fmaf(v.x, w[0], s0);  s1 = fmaf(v.x, w[1], s1);
        s0 = fmaf(v.y, w[2], s0);  s1 = fmaf(v.y, w[3], s1);
        s0 = fmaf(v.z, w[4], s0);  s1 = fmaf(v.z, w[5], s1);
        s0 = fmaf(v.w, w[6], s0);  s1 = fmaf(v.w, w[7], s1);
    }
    out[2 * m + 0] = s0;
    out[2 * m + 1] = s1;
}

extern "C" void kernel_launch(void* const* d_in, const int* in_sizes, int n_in,
                              void* d_out, int out_size)
{
    const float* x     = (const float*)d_in[0];
    const float* adj   = (const float*)d_in[1];
    const float* W1    = (const float*)d_in[2];
    const float* b1    = (const float*)d_in[3];
    const float* W2    = (const float*)d_in[4];
    const float* b2    = (const float*)d_in[5];
    const float* W3    = (const float*)d_in[6];
    const float* b3    = (const float*)d_in[7];
    const float* W4    = (const float*)d_in[8];
    const float* b4    = (const float*)d_in[9];
    const float* cW1   = (const float*)d_in[10];
    const float* cb1   = (const float*)d_in[11];
    const float* alpha = (const float*)d_in[12];
    const float* cW2   = (const float*)d_in[13];
    const float* cb2   = (const float*)d_in[14];
    float* out = (float*)d_out;

    float *bufA, *bufB, *agg;
    cudaGetSymbolAddress((void**)&bufA, g_bufA);
    cudaGetSymbolAddress((void**)&bufB, g_bufB);
    cudaGetSymbolAddress((void**)&agg,  g_agg);

    const size_t sAdj = (size_t)Nn * Nn;
    auto grid = [](int F, int M, int batches) { return dim3(F / BN, M / BM, batches); };

    // ---- Layer 1 (in d=256, out 512) ----
    gemm_cat_kernel<<<grid(D0, Nn, Bb), 256>>>(        // agg0 = adj @ x
        adj, sAdj, Nn, nullptr, 0, 0,
        x, (size_t)Nn * D0, nullptr, nullptr,
        agg, (size_t)Nn * D0, Nn, D0, 0);
    gemm_cat_kernel<<<grid(H, Nn, Bb), 256>>>(         // h1 = relu([x|agg0] @ W1 + b1)
        x, (size_t)Nn * D0, D0, agg, (size_t)Nn * D0, D0,
        W1, 0, b1, nullptr,
        bufA, (size_t)Nn * H, Nn, H, 1);

    // ---- Layer 2 (512 -> 512) ----
    gemm_cat_kernel<<<grid(H, Nn, Bb), 256>>>(
        adj, sAdj, Nn, nullptr, 0, 0,
        bufA, (size_t)Nn * H, nullptr, nullptr,
        agg, (size_t)Nn * H, Nn, H, 0);
    gemm_cat_kernel<<<grid(H, Nn, Bb), 256>>>(
        bufA, (size_t)Nn * H, H, agg, (size_t)Nn * H, H,
        W2, 0, b2, nullptr,
        bufB, (size_t)Nn * H, Nn, H, 1);

    // ---- Layer 3 (512 -> 256) ----
    gemm_cat_kernel<<<grid(H, Nn, Bb), 256>>>(
        adj, sAdj, Nn, nullptr, 0, 0,
        bufB, (size_t)Nn * H, nullptr, nullptr,
        agg, (size_t)Nn * H, Nn, H, 0);
    gemm_cat_kernel<<<grid(HH, Nn, Bb), 256>>>(
        bufB, (size_t)Nn * H, H, agg, (size_t)Nn * H, H,
        W3, 0, b3, nullptr,
        bufA, (size_t)Nn * HH, Nn, HH, 1);

    // ---- Layer 4 (256 -> 256) ----
    gemm_cat_kernel<<<grid(HH, Nn, Bb), 256>>>(
        adj, sAdj, Nn, nullptr, 0, 0,
        bufA, (size_t)Nn * HH, nullptr, nullptr,
        agg, (size_t)Nn * HH, Nn, HH, 0);
    gemm_cat_kernel<<<grid(HH, Nn, Bb), 256>>>(
        bufA, (size_t)Nn * HH, HH, agg, (size_t)Nn * HH, HH,
        W4, 0, b4, nullptr,
        bufB, (size_t)Nn * HH, Nn, HH, 1);

    // ---- Classifier: Linear + PReLU ----
    gemm_cat_kernel<<<grid(HH, Nn, Bb), 256>>>(
        bufB, (size_t)Nn * HH, HH, nullptr, 0, 0,
        cW1, 0, cb1, alpha,
        bufA, (size_t)Nn * HH, Nn, HH, 2);

    // ---- Final projection to 2 classes ----
    int Mrows = Bb * Nn;
    final_proj_kernel<<<(Mrows + 255) / 256, 256>>>(bufA, cW2, cb2, out, Mrows, HH);
}

// round 10
// speedup vs baseline: 1.9846x; 1.9846x over previous
#include <cuda_runtime.h>
#include <cuda_bf16.h>
#include <cstdint>
#include <cstddef>

// ===========================================================================
// GCN via mma.sync bf16 3-term split GEMMs (compute_103-safe tensor path).
// A*B ~= Ah*Bh + Ah*Bl + Al*Bh, fp32 accumulators (dropped term ~2^-18 rel).
// gemm_mma: C[b] = act([A1|A2] @ B^T + bias); CTA tile 128x128, K-chunk 32,
// 8 warps x (32x64) warp tiles, m16n8k16 HMMA, ldmatrix.x4, 80B-padded smem,
// register-prefetch double buffering. Concat virtual (K1 % 32 == 0).
// ===========================================================================

static const int Bb = 32, Nn = 1024, D0 = 256, H = 512, HH = 256;

// ---- device scratch (allocation-free) ----
__device__ float g_h1 [32u * 1024u * 512u];
__device__ float g_h2 [32u * 1024u * 512u];
__device__ float g_agg[32u * 1024u * 512u];
__device__ __nv_bfloat16 g_T1h[32u * 512u * 1024u];
__device__ __nv_bfloat16 g_T1l[32u * 512u * 1024u];
__device__ __nv_bfloat16 g_T2h[32u * 512u * 1024u];
__device__ __nv_bfloat16 g_T2l[32u * 512u * 1024u];
__device__ __nv_bfloat16 g_W1h[512u * 512u],  g_W1l[512u * 512u];
__device__ __nv_bfloat16 g_W2h[512u * 1024u], g_W2l[512u * 1024u];
__device__ __nv_bfloat16 g_W3h[256u * 1024u], g_W3l[256u * 1024u];
__device__ __nv_bfloat16 g_W4h[256u * 512u],  g_W4l[256u * 512u];
__device__ __nv_bfloat16 g_Wch[256u * 256u],  g_Wcl[256u * 256u];

static __device__ __forceinline__ uint32_t smem_u32(const void* p) {
    uint32_t a;
    asm("{ .reg .u64 t; cvta.to.shared.u64 t, %1; cvt.u32.u64 %0, t; }"
        : "=r"(a) : "l"(p));
    return a;
}
static __device__ __forceinline__ void ldsm4(uint32_t* r, uint32_t addr) {
    asm volatile("ldmatrix.sync.aligned.m8n8.x4.shared.b16 {%0,%1,%2,%3}, [%4];"
        : "=r"(r[0]), "=r"(r[1]), "=r"(r[2]), "=r"(r[3]) : "r"(addr));
}
static __device__ __forceinline__ void mma16816(float* c, const uint32_t* a,
                                                const uint32_t* b) {
    asm volatile(
        "mma.sync.aligned.m16n8k16.row.col.f32.bf16.bf16.f32 "
        "{%0,%1,%2,%3}, {%4,%5,%6,%7}, {%8,%9}, {%0,%1,%2,%3};"
        : "+f"(c[0]), "+f"(c[1]), "+f"(c[2]), "+f"(c[3])
        : "r"(a[0]), "r"(a[1]), "r"(a[2]), "r"(a[3]), "r"(b[0]), "r"(b[1]));
}

#define SP 40                    // padded row stride (bf16): 32 data + 8 pad = 80B
#define STAGE_E 20480            // bf16 units per stage: Ah,Al,Bh,Bl @ 128*SP each
#define OFF_AL  5120
#define OFF_BH  10240
#define OFF_BL  15360
#define DSMEM_BYTES (2 * STAGE_E * 2)

__global__ __launch_bounds__(256, 1)
void gemm_mma(const float* __restrict__ A1, size_t sA1, int K1,
              const float* __restrict__ A2, size_t sA2, int K2,
              const __nv_bfloat16* __restrict__ Bhi,
              const __nv_bfloat16* __restrict__ Blo, size_t sB,
              const float* __restrict__ bias, const float* __restrict__ alpha,
              float* __restrict__ C, size_t sC, int F, int act)
{
    extern __shared__ __nv_bfloat16 sm[];
    const int tid = threadIdx.x, wid = tid >> 5, lane = tid & 31;
    const int b = blockIdx.z, m0 = blockIdx.y * 128, n0 = blockIdx.x * 128;
    const int Ktot = K1 + K2;

    const float* A1b = A1 + (size_t)b * sA1;
    const float* A2b = A2 ? (A2 + (size_t)b * sA2) : nullptr;
    const __nv_bfloat16* Bhb = Bhi + (size_t)b * sB;
    const __nv_bfloat16* Blb = Blo + (size_t)b * sB;
    float* Cb = C + (size_t)b * sC;

    const int warp_m = wid & 3, warp_n = wid >> 2;
    const int mbase = warp_m * 32, nbase = warp_n * 64;

    float c[2][8][4];
    #pragma unroll
    for (int i = 0; i < 2; i++)
        #pragma unroll
        for (int j = 0; j < 8; j++)
            #pragma unroll
            for (int q = 0; q < 4; q++) c[i][j][q] = 0.f;

    // ---- global prefetch regs ----
    float4 pa[4];
    uint4  pbh[2], pbl[2];
    auto ldg_chunk = [&](int kt) {
        const float* Asrc; int lda, kofs;
        if (kt < K1) { Asrc = A1b; lda = K1; kofs = kt; }
        else         { Asrc = A2b; lda = K2; kofs = kt - K1; }
        #pragma unroll
        for (int i = 0; i < 4; i++) {
            int u = tid + i * 256;
            int r = u >> 3, c4 = u & 7;              // 128 rows x 8 float4
            pa[i] = *(const float4*)(Asrc + (size_t)(m0 + r) * lda + kofs + c4 * 4);
        }
        #pragma unroll
        for (int i = 0; i < 2; i++) {
            int u = tid + i * 256;
            int r = u >> 2, c8 = u & 3;              // 128 rows x 4 uint4
            size_t g = (size_t)(n0 + r) * Ktot + kt + c8 * 8;
            pbh[i] = *(const uint4*)(Bhb + g);
            pbl[i] = *(const uint4*)(Blb + g);
        }
    };
    auto sts_chunk = [&](int s) {
        __nv_bfloat16* Ah = sm + s * STAGE_E;
        #pragma unroll
        for (int i = 0; i < 4; i++) {
            int u = tid + i * 256;
            int r = u >> 3, c4 = u & 7;
            float4 f = pa[i];
            __nv_bfloat16 h0 = __float2bfloat16_rn(f.x);
            __nv_bfloat16 h1 = __float2bfloat16_rn(f.y);
            __nv_bfloat16 h2 = __float2bfloat16_rn(f.z);
            __nv_bfloat16 h3 = __float2bfloat16_rn(f.w);
            __nv_bfloat16 l0 = __float2bfloat16_rn(f.x - __bfloat162float(h0));
            __nv_bfloat16 l1 = __float2bfloat16_rn(f.y - __bfloat162float(h1));
            __nv_bfloat16 l2 = __float2bfloat16_rn(f.z - __bfloat162float(h2));
            __nv_bfloat16 l3 = __float2bfloat16_rn(f.w - __bfloat162float(h3));
            uint2 hv, lv;
            hv.x = (uint32_t)__bfloat16_as_ushort(h0) | ((uint32_t)__bfloat16_as_ushort(h1) << 16);
            hv.y = (uint32_t)__bfloat16_as_ushort(h2) | ((uint32_t)__bfloat16_as_ushort(h3) << 16);
            lv.x = (uint32_t)__bfloat16_as_ushort(l0) | ((uint32_t)__bfloat16_as_ushort(l1) << 16);
            lv.y = (uint32_t)__bfloat16_as_ushort(l2) | ((uint32_t)__bfloat16_as_ushort(l3) << 16);
            *(uint2*)(Ah + r * SP + c4 * 4) = hv;
            *(uint2*)(Ah + OFF_AL + r * SP + c4 * 4) = lv;
        }
        #pragma unroll
        for (int i = 0; i < 2; i++) {
            int u = tid + i * 256;
            int r = u >> 2, c8 = u & 3;
            *(uint4*)(Ah + OFF_BH + r * SP + c8 * 8) = pbh[i];
            *(uint4*)(Ah + OFF_BL + r * SP + c8 * 8) = pbl[i];
        }
    };

    // lane-derived ldmatrix row/col offsets (verified vs PTX fragment layouts)
    const int a_r = ((lane >> 3) & 1) * 8 + (lane & 7);
    const int a_k = (lane >> 4) * 8;
    const int b_r = ((lane >> 4) & 1) * 8 + (lane & 7);
    const int b_k = ((lane >> 3) & 1) * 8;
    const uint32_t smbase = smem_u32(sm);

    ldg_chunk(0);
    sts_chunk(0);
    __syncthreads();

    const int nch = Ktot / 32;
    for (int ch = 0; ch < nch; ch++) {
        int s = ch & 1;
        if (ch + 1 < nch) ldg_chunk((ch + 1) * 32);

        uint32_t base = smbase + s * (STAGE_E * 2);
        #pragma unroll
        for (int ks = 0; ks < 32; ks += 16) {
            uint32_t ah[2][4], av[2][4], bh[4][4], bv[4][4];
            #pragma unroll
            for (int mf = 0; mf < 2; mf++) {
                uint32_t ad = base + (uint32_t)(((mbase + mf * 16 + a_r) * SP + ks + a_k) * 2);
                ldsm4(ah[mf], ad);
                ldsm4(av[mf], ad + OFF_AL * 2);
            }
            #pragma unroll
            for (int p = 0; p < 4; p++) {
                uint32_t ad = base + (uint32_t)(OFF_BH * 2 +
                              ((nbase + p * 16 + b_r) * SP + ks + b_k) * 2);
                ldsm4(bh[p], ad);
                ldsm4(bv[p], ad + (OFF_BL - OFF_BH) * 2);
            }
            #pragma unroll
            for (int mf = 0; mf < 2; mf++)
                #pragma unroll
                for (int p = 0; p < 4; p++)
                    #pragma unroll
                    for (int q = 0; q < 2; q++) {
                        float* cc = c[mf][p * 2 + q];
                        mma16816(cc, ah[mf], &bh[p][2 * q]);   // Ah*Bh
                        mma16816(cc, ah[mf], &bv[p][2 * q]);   // Ah*Bl
                        mma16816(cc, av[mf], &bh[p][2 * q]);   // Al*Bh
                    }
        }

        if (ch + 1 < nch) sts_chunk(s ^ 1);
        __syncthreads();
    }

    // ---- epilogue: bias + activation, direct float2 stores ----
    const int trow = lane >> 2, tc2 = (lane & 3) * 2;
    #pragma unroll
    for (int mf = 0; mf < 2; mf++)
        #pragma unroll
        for (int nf = 0; nf < 8; nf++) {
            int row = m0 + mbase + mf * 16 + trow;
            int col = n0 + nbase + nf * 8 + tc2;
            float v[4] = {c[mf][nf][0], c[mf][nf][1], c[mf][nf][2], c[mf][nf][3]};
            if (bias) {
                float b0 = __ldg(bias + col), b1 = __ldg(bias + col + 1);
                v[0] += b0; v[1] += b1; v[2] += b0; v[3] += b1;
            }
            if (act == 1) {
                #pragma unroll
                for (int q = 0; q < 4; q++) v[q] = v[q] > 0.f ? v[q] : 0.f;
            } else if (act == 2) {
                float a0 = __ldg(alpha + col), a1 = __ldg(alpha + col + 1);
                v[0] = v[0] > 0.f ? v[0] : a0 * v[0];
                v[1] = v[1] > 0.f ? v[1] : a1 * v[1];
                v[2] = v[2] > 0.f ? v[2] : a0 * v[2];
                v[3] = v[3] > 0.f ? v[3] : a1 * v[3];
            }
            *(float2*)(Cb + (size_t)row * F + col)       = make_float2(v[0], v[1]);
            *(float2*)(Cb + (size_t)(row + 8) * F + col) = make_float2(v[2], v[3]);
        }
}

// ---- transpose + bf16 hi/lo split: src fp32 [R,C] -> dst bf16 [C,R] ----
__global__ void tsplit_kernel(const float* __restrict__ src, size_t sstride,
                              __nv_bfloat16* __restrict__ hiT,
                              __nv_bfloat16* __restrict__ loT,
                              size_t dstride, int R, int C)
{
    __shared__ float t[32][33];
    const int b = blockIdx.z;
    const float* s = src + (size_t)b * sstride;
    __nv_bfloat16* hb = hiT + (size_t)b * dstride;
    __nv_bfloat16* lb = loT + (size_t)b * dstride;
    const int c0 = blockIdx.x * 32, r0 = blockIdx.y * 32;
    const int tx = threadIdx.x, ty = threadIdx.y;
    #pragma unroll
    for (int i = 0; i < 4; i++)
        t[ty + i * 8][tx] = s[(size_t)(r0 + ty + i * 8) * C + c0 + tx];
    __syncthreads();
    #pragma unroll
    for (int i = 0; i < 4; i++) {
        float v = t[tx][ty + i * 8];
        __nv_bfloat16 h = __float2bfloat16_rn(v);
        __nv_bfloat16 l = __float2bfloat16_rn(v - __bfloat162float(h));
        size_t d = (size_t)(c0 + ty + i * 8) * R + r0 + tx;
        hb[d] = h;
        lb[d] = l;
    }
}

// ---- final projection: out[m,0:2] = h[m,:] @ cW2 + cb2 ----
__global__ __launch_bounds__(256)
void final_proj_kernel(const float* __restrict__ h,
                       const float* __restrict__ cW2,
                       const float* __restrict__ cb2,
                       float* __restrict__ out, int Mrows, int K)
{
    int m = blockIdx.x * blockDim.x + threadIdx.x;
    if (m >= Mrows) return;
    const float4* hr = (const float4*)(h + (size_t)m * K);
    float s0 = cb2[0], s1 = cb2[1];
    #pragma unroll 4
    for (int k4 = 0; k4 < K / 4; k4++) {
        float4 v = hr[k4];
        const float* w = cW2 + 8 * k4;
        s0 = fmaf(v.x, w[0], s0);  s1 = fmaf(v.x, w[1], s1);
        s0 = fmaf(v.y, w[2], s0);  s1 = fmaf(v.y, w[3], s1);
        s0 = fmaf(v.z, w[4], s0);  s1 = fmaf(v.z, w[5], s1);
        s0 = fmaf(v.w, w[6], s0);  s1 = fmaf(v.w, w[7], s1);
    }
    out[2 * m + 0] = s0;
    out[2 * m + 1] = s1;
}

extern "C" void kernel_launch(void* const* d_in, const int* in_sizes, int n_in,
                              void* d_out, int out_size)
{
    const float* x     = (const float*)d_in[0];
    const float* adj   = (const float*)d_in[1];
    const float* W1    = (const float*)d_in[2];
    const float* b1    = (const float*)d_in[3];
    const float* W2    = (const float*)d_in[4];
    const float* b2    = (const float*)d_in[5];
    const float* W3    = (const float*)d_in[6];
    const float* b3    = (const float*)d_in[7];
    const float* W4    = (const float*)d_in[8];
    const float* b4    = (const float*)d_in[9];
    const float* cW1   = (const float*)d_in[10];
    const float* cb1   = (const float*)d_in[11];
    const float* alpha = (const float*)d_in[12];
    const float* cW2   = (const float*)d_in[13];
    const float* cb2   = (const float*)d_in[14];
    float* out = (float*)d_out;

    float *h1, *h2, *agg;
    __nv_bfloat16 *T1h, *T1l, *T2h, *T2l;
    __nv_bfloat16 *W1h, *W1l, *W2h, *W2l, *W3h, *W3l, *W4h, *W4l, *Wch, *Wcl;
    cudaGetSymbolAddress((void**)&h1,  g_h1);
    cudaGetSymbolAddress((void**)&h2,  g_h2);
    cudaGetSymbolAddress((void**)&agg, g_agg);
    cudaGetSymbolAddress((void**)&T1h, g_T1h);
    cudaGetSymbolAddress((void**)&T1l, g_T1l);
    cudaGetSymbolAddress((void**)&T2h, g_T2h);
    cudaGetSymbolAddress((void**)&T2l, g_T2l);
    cudaGetSymbolAddress((void**)&W1h, g_W1h);
    cudaGetSymbolAddress((void**)&W1l, g_W1l);
    cudaGetSymbolAddress((void**)&W2h, g_W2h);
    cudaGetSymbolAddress((void**)&W2l, g_W2l);
    cudaGetSymbolAddress((void**)&W3h, g_W3h);
    cudaGetSymbolAddress((void**)&W3l, g_W3l);
    cudaGetSymbolAddress((void**)&W4h, g_W4h);
    cudaGetSymbolAddress((void**)&W4l, g_W4l);
    cudaGetSymbolAddress((void**)&Wch, g_Wch);
    cudaGetSymbolAddress((void**)&Wcl, g_Wcl);

    cudaFuncSetAttribute(gemm_mma, cudaFuncAttributeMaxDynamicSharedMemorySize,
                         DSMEM_BYTES);

    const size_t sAdj = (size_t)Nn * Nn;
    const size_t sX   = (size_t)Nn * D0;
    const size_t sH   = (size_t)Nn * H;
    const size_t sHH  = (size_t)Nn * HH;
    dim3 tb(32, 8);

    // weight transpose-splits (tiny)
    tsplit_kernel<<<dim3(H  / 32, (2 * D0) / 32, 1), tb>>>(W1,  0, W1h, W1l, 0, 2 * D0, H);
    tsplit_kernel<<<dim3(H  / 32, (2 * H)  / 32, 1), tb>>>(W2,  0, W2h, W2l, 0, 2 * H,  H);
    tsplit_kernel<<<dim3(HH / 32, (2 * H)  / 32, 1), tb>>>(W3,  0, W3h, W3l, 0, 2 * H,  HH);
    tsplit_kernel<<<dim3(HH / 32, (2 * HH) / 32, 1), tb>>>(W4,  0, W4h, W4l, 0, 2 * HH, HH);
    tsplit_kernel<<<dim3(HH / 32, HH / 32, 1),       tb>>>(cW1, 0, Wch, Wcl, 0, HH, HH);
    // xT
    tsplit_kernel<<<dim3(D0 / 32, Nn / 32, Bb), tb>>>(x, sX, T1h, T1l, (size_t)D0 * Nn, Nn, D0);

    // ---- Layer 1 ----
    gemm_mma<<<dim3(D0 / 128, 8, Bb), 256, DSMEM_BYTES>>>(
        adj, sAdj, Nn, nullptr, 0, 0, T1h, T1l, (size_t)D0 * Nn,
        nullptr, nullptr, agg, sX, D0, 0);
    gemm_mma<<<dim3(H / 128, 8, Bb), 256, DSMEM_BYTES>>>(
        x, sX, D0, agg, sX, D0, W1h, W1l, 0,
        b1, nullptr, h1, sH, H, 1);

    // ---- Layer 2 ----
    tsplit_kernel<<<dim3(H / 32, Nn / 32, Bb), tb>>>(h1, sH, T2h, T2l, (size_t)H * Nn, Nn, H);
    gemm_mma<<<dim3(H / 128, 8, Bb), 256, DSMEM_BYTES>>>(
        adj, sAdj, Nn, nullptr, 0, 0, T2h, T2l, (size_t)H * Nn,
        nullptr, nullptr, agg, sH, H, 0);
    gemm_mma<<<dim3(H / 128, 8, Bb), 256, DSMEM_BYTES>>>(
        h1, sH, H, agg, sH, H, W2h, W2l, 0,
        b2, nullptr, h2, sH, H, 1);

    // ---- Layer 3 ----
    tsplit_kernel<<<dim3(H / 32, Nn / 32, Bb), tb>>>(h2, sH, T1h, T1l, (size_t)H * Nn, Nn, H);
    gemm_mma<<<dim3(H / 128, 8, Bb), 256, DSMEM_BYTES>>>(
        adj, sAdj, Nn, nullptr, 0, 0, T1h, T1l, (size_t)H * Nn,
        nullptr, nullptr, agg, sH, H, 0);
    gemm_mma<<<dim3(HH / 128, 8, Bb), 256, DSMEM_BYTES>>>(
        h2, sH, H, agg, sH, H, W3h, W3l, 0,
        b3, nullptr, h1, sHH, HH, 1);

    // ---- Layer 4 ----
    tsplit_kernel<<<dim3(HH / 32, Nn / 32, Bb), tb>>>(h1, sHH, T2h, T2l, (size_t)HH * Nn, Nn, HH);
    gemm_mma<<<dim3(HH / 128, 8, Bb), 256, DSMEM_BYTES>>>(
        adj, sAdj, Nn, nullptr, 0, 0, T2h, T2l, (size_t)HH * Nn,
        nullptr, nullptr, agg, sHH, HH, 0);
    gemm_mma<<<dim3(HH / 128, 8, Bb), 256, DSMEM_BYTES>>>(
        h1, sHH, HH, agg, sHH, HH, W4h, W4l, 0,
        b4, nullptr, h2, sHH, HH, 1);

    // ---- Classifier Linear + PReLU ----
    gemm_mma<<<dim3(HH / 128, 8, Bb), 256, DSMEM_BYTES>>>(
        h2, sHH, HH, nullptr, 0, 0, Wch, Wcl, 0,
        cb1, alpha, h1, sHH, HH, 2);

    // ---- Final projection ----
    int Mrows = Bb * Nn;
    final_proj_kernel<<<(Mrows + 255) / 256, 256>>>(h1, cW2, cb2, out, Mrows, HH);
}